// round 12
// baseline (speedup 1.0000x reference)
#include <cuda_runtime.h>

#define SEQ_LEN  512
#define PRED_LEN 192
#define ENC_IN   512
#define BATCH    128
#define CSPLIT   8
#define CH_PER_CTA (ENC_IN / CSPLIT)       // 64 channels -> 16 float4 lanes
#define LANES    (CH_PER_CTA / 4)          // 16
#define NSUB     16                        // row subgroups
#define ROWS_PER_THREAD (SEQ_LEN / NSUB)   // 32
#define NT       (LANES * NSUB)            // 256 threads

// Fused: grid (BATCH, CSPLIT) = 1024 CTAs, block 256, 8 CTAs/SM (single wave,
// 64 warps/SM). Reads stream with __ldcs; all stores evict-first (__stcs).
// All independent zero-stores are issued BEFORE the reduction barrier so they
// drain while the smem reduce + dec/t dependency stall plays out.
__global__ __launch_bounds__(NT, 8)
void fused_trend_kernel(const float* __restrict__ x_enc, float* __restrict__ out) {
    const int b    = blockIdx.x;
    const int cg   = blockIdx.y;
    const int t    = threadIdx.x;
    const int lane = t & (LANES - 1);      // float4 column (0..15)
    const int rsub = t >> 4;               // row subgroup (0..15)
    const int c0   = cg * CH_PER_CTA;

    const size_t SEC = (size_t)BATCH * PRED_LEN * ENC_IN;   // floats per tensor
    const size_t tile_f = (size_t)b * PRED_LEN * ENC_IN + c0;
    const float4 zero = make_float4(0.f, 0.f, 0.f, 0.f);

    float4* __restrict__ sou = reinterpret_cast<float4*>(out + 2 * SEC + tile_f);

    // ---- s_out zeros, first half (rows 0..95) — overlaps the read phase ----
    #pragma unroll
    for (int idx = t; idx < (PRED_LEN / 2) * LANES; idx += NT) {
        int row = idx >> 4;
        int c4  = idx & (LANES - 1);
        __stcs(&sou[(size_t)row * (ENC_IN / 4) + c4], zero);
    }

    // ---- Reduction over L: 32 rows/thread, streaming loads ----
    const float4* __restrict__ px =
        reinterpret_cast<const float4*>(x_enc + (size_t)b * SEQ_LEN * ENC_IN + c0);

    float4 sy  = zero;
    float4 sty = zero;
    #pragma unroll 4
    for (int i = 0; i < ROWS_PER_THREAD; ++i) {
        int r = i * NSUB + rsub;
        float4 v = __ldcs(&px[(size_t)r * (ENC_IN / 4) + lane]);
        float tc = (float)(r - SEQ_LEN);          // t in [-512, -1]
        sy.x += v.x;  sy.y += v.y;  sy.z += v.z;  sy.w += v.w;
        sty.x = fmaf(tc, v.x, sty.x);
        sty.y = fmaf(tc, v.y, sty.y);
        sty.z = fmaf(tc, v.z, sty.z);
        sty.w = fmaf(tc, v.w, sty.w);
    }

    __shared__ float4 red_sy[NSUB][LANES];
    __shared__ float4 red_sty[NSUB][LANES];
    __shared__ float4 sI4[LANES];
    __shared__ float4 sS4[LANES];

    red_sy[rsub][lane]  = sy;
    red_sty[rsub][lane] = sty;

    // ---- s_out zeros, second half — independent; drains during barrier ----
    #pragma unroll
    for (int idx = t; idx < (PRED_LEN / 2) * LANES; idx += NT) {
        int row = (idx >> 4) + PRED_LEN / 2;
        int c4  = idx & (LANES - 1);
        __stcs(&sou[(size_t)row * (ENC_IN / 4) + c4], zero);
    }

    __syncthreads();

    if (t < LANES) {
        float4 a = red_sy[0][t];
        float4 c = red_sty[0][t];
        #pragma unroll
        for (int k = 1; k < NSUB; ++k) {
            float4 u = red_sy[k][t];
            float4 w = red_sty[k][t];
            a.x += u.x; a.y += u.y; a.z += u.z; a.w += u.w;
            c.x += w.x; c.y += w.y; c.z += w.z; c.w += w.w;
        }
        // Normal-equation constants for t = -512..-1 (exact in fp32):
        const float S0  = 512.0f;
        const float S1  = -131328.0f;
        const float S2  = 44870400.0f;
        const float det = 5726601216.0f;

        float4 I, S;
        I.x = (S2 * a.x - S1 * c.x) / det;  S.x = (S0 * c.x - S1 * a.x) / det;
        I.y = (S2 * a.y - S1 * c.y) / det;  S.y = (S0 * c.y - S1 * a.y) / det;
        I.z = (S2 * a.z - S1 * c.z) / det;  S.z = (S0 * c.z - S1 * a.z) / det;
        I.w = (S2 * a.w - S1 * c.w) / det;  S.w = (S0 * c.w - S1 * a.w) / det;
        sI4[t] = I;
        sS4[t] = S;
    }
    __syncthreads();

    // ---- Write dec_out and t_out (identical values), streaming stores ----
    float4* __restrict__ dec = reinterpret_cast<float4*>(out + tile_f);
    float4* __restrict__ tou = reinterpret_cast<float4*>(out + SEC + tile_f);

    #pragma unroll 4
    for (int idx = t; idx < PRED_LEN * LANES; idx += NT) {
        int row = idx >> 4;
        int c4  = idx & (LANES - 1);
        float tn = (float)(SEQ_LEN - PRED_LEN + row);   // 320..511
        float4 I = sI4[c4];
        float4 S = sS4[c4];
        float4 v;
        v.x = fmaf(S.x, tn, I.x);
        v.y = fmaf(S.y, tn, I.y);
        v.z = fmaf(S.z, tn, I.z);
        v.w = fmaf(S.w, tn, I.w);
        size_t off = (size_t)row * (ENC_IN / 4) + c4;
        __stcs(&dec[off], v);
        __stcs(&tou[off], v);
    }
}

extern "C" void kernel_launch(void* const* d_in, const int* in_sizes, int n_in,
                              void* d_out, int out_size) {
    const float* x_enc = (const float*)d_in[0];
    float* out = (float*)d_out;
    fused_trend_kernel<<<dim3(BATCH, CSPLIT), NT>>>(x_enc, out);
}

// round 14
// speedup vs baseline: 1.0329x; 1.0329x over previous
#include <cuda_runtime.h>

#define SEQ_LEN  512
#define PRED_LEN 192
#define ENC_IN   512
#define BATCH    128
#define CSPLIT   8
#define CH_PER_CTA (ENC_IN / CSPLIT)       // 64 channels -> 16 float4 lanes
#define LANES    (CH_PER_CTA / 4)          // 16
#define NSUB     16                        // row subgroups
#define ROWS_PER_THREAD (SEQ_LEN / NSUB)   // 32
#define NT       (LANES * NSUB)            // 256 threads

// Fused: grid (BATCH, CSPLIT) = 1024 CTAs, block 256.
// __launch_bounds__(256, 8): 32 regs -> 8 CTAs/SM resident, 64 warps/SM,
// single wave (1184 slots >= 1024 CTAs). Reads stream (__ldcs), stores are
// evict-first (__stcs). Zero-drain split: half before the read phase (overlaps
// reads), half strictly after dec/t writes (fills the store-only tail).
__global__ __launch_bounds__(NT, 8)
void fused_trend_kernel(const float* __restrict__ x_enc, float* __restrict__ out) {
    const int b    = blockIdx.x;
    const int cg   = blockIdx.y;
    const int t    = threadIdx.x;
    const int lane = t & (LANES - 1);      // float4 column (0..15)
    const int rsub = t >> 4;               // row subgroup (0..15)
    const int c0   = cg * CH_PER_CTA;

    const size_t SEC = (size_t)BATCH * PRED_LEN * ENC_IN;   // floats per tensor
    const size_t tile_f = (size_t)b * PRED_LEN * ENC_IN + c0;
    const float4 zero = make_float4(0.f, 0.f, 0.f, 0.f);

    float4* __restrict__ sou = reinterpret_cast<float4*>(out + 2 * SEC + tile_f);

    // ---- s_out zeros, first half (rows 0..95) — overlaps the read phase ----
    #pragma unroll
    for (int idx = t; idx < (PRED_LEN / 2) * LANES; idx += NT) {
        int row = idx >> 4;
        int c4  = idx & (LANES - 1);
        __stcs(&sou[(size_t)row * (ENC_IN / 4) + c4], zero);
    }

    // ---- Reduction over L: 32 rows/thread, streaming loads ----
    const float4* __restrict__ px =
        reinterpret_cast<const float4*>(x_enc + (size_t)b * SEQ_LEN * ENC_IN + c0);

    float4 sy  = zero;
    float4 sty = zero;
    #pragma unroll 4
    for (int i = 0; i < ROWS_PER_THREAD; ++i) {
        int r = i * NSUB + rsub;
        float4 v = __ldcs(&px[(size_t)r * (ENC_IN / 4) + lane]);
        float tc = (float)(r - SEQ_LEN);          // t in [-512, -1]
        sy.x += v.x;  sy.y += v.y;  sy.z += v.z;  sy.w += v.w;
        sty.x = fmaf(tc, v.x, sty.x);
        sty.y = fmaf(tc, v.y, sty.y);
        sty.z = fmaf(tc, v.z, sty.z);
        sty.w = fmaf(tc, v.w, sty.w);
    }

    __shared__ float4 red_sy[NSUB][LANES];
    __shared__ float4 red_sty[NSUB][LANES];
    __shared__ float4 sI4[LANES];
    __shared__ float4 sS4[LANES];

    red_sy[rsub][lane]  = sy;
    red_sty[rsub][lane] = sty;
    __syncthreads();

    if (t < LANES) {
        float4 a = red_sy[0][t];
        float4 c = red_sty[0][t];
        #pragma unroll
        for (int k = 1; k < NSUB; ++k) {
            float4 u = red_sy[k][t];
            float4 w = red_sty[k][t];
            a.x += u.x; a.y += u.y; a.z += u.z; a.w += u.w;
            c.x += w.x; c.y += w.y; c.z += w.z; c.w += w.w;
        }
        // Normal-equation constants for t = -512..-1 (exact in fp32):
        const float S0  = 512.0f;
        const float S1  = -131328.0f;
        const float S2  = 44870400.0f;
        const float det = 5726601216.0f;

        float4 I, S;
        I.x = (S2 * a.x - S1 * c.x) / det;  S.x = (S0 * c.x - S1 * a.x) / det;
        I.y = (S2 * a.y - S1 * c.y) / det;  S.y = (S0 * c.y - S1 * a.y) / det;
        I.z = (S2 * a.z - S1 * c.z) / det;  S.z = (S0 * c.z - S1 * a.z) / det;
        I.w = (S2 * a.w - S1 * c.w) / det;  S.w = (S0 * c.w - S1 * a.w) / det;
        sI4[t] = I;
        sS4[t] = S;
    }
    __syncthreads();

    // ---- Write dec_out and t_out (identical values), streaming stores ----
    float4* __restrict__ dec = reinterpret_cast<float4*>(out + tile_f);
    float4* __restrict__ tou = reinterpret_cast<float4*>(out + SEC + tile_f);

    #pragma unroll 4
    for (int idx = t; idx < PRED_LEN * LANES; idx += NT) {
        int row = idx >> 4;
        int c4  = idx & (LANES - 1);
        float tn = (float)(SEQ_LEN - PRED_LEN + row);   // 320..511
        float4 I = sI4[c4];
        float4 S = sS4[c4];
        float4 v;
        v.x = fmaf(S.x, tn, I.x);
        v.y = fmaf(S.y, tn, I.y);
        v.z = fmaf(S.z, tn, I.z);
        v.w = fmaf(S.w, tn, I.w);
        size_t off = (size_t)row * (ENC_IN / 4) + c4;
        __stcs(&dec[off], v);
        __stcs(&tou[off], v);
    }

    // ---- s_out zeros, second half (rows 96..191) ----
    #pragma unroll
    for (int idx = t; idx < (PRED_LEN / 2) * LANES; idx += NT) {
        int row = (idx >> 4) + PRED_LEN / 2;
        int c4  = idx & (LANES - 1);
        __stcs(&sou[(size_t)row * (ENC_IN / 4) + c4], zero);
    }
}

extern "C" void kernel_launch(void* const* d_in, const int* in_sizes, int n_in,
                              void* d_out, int out_size) {
    const float* x_enc = (const float*)d_in[0];
    float* out = (float*)d_out;
    fused_trend_kernel<<<dim3(BATCH, CSPLIT), NT>>>(x_enc, out);
}